// round 6
// baseline (speedup 1.0000x reference)
#include <cuda_runtime.h>

// ---------------------------------------------------------------------------
// HiLo attention block, B=1, H=W=96, DIM=128, WS=2
// ---------------------------------------------------------------------------

#define NPIX 9216          // 96*96
#define NS   2304          // 48*48 pooled tokens
#define ATTN_SCALE 0.25f   // 16^-0.5

typedef unsigned long long u64;

// -------------------- scratch (device globals; no allocation) --------------
__device__ float g_low [NS   * 128];   // pooled features
__device__ float g_l2h [NPIX * 32];    // pixel-shuffled low
__device__ float g_high[NPIX * 128];   // high-frequency residual
__device__ float g_lq  [NPIX * 64];    // low-path queries  [n][h*16+d]
__device__ float g_lkv [NS   * 128];   // low-path K|V      [m][kv*64+h*16+d]
__device__ float g_hqkv[NPIX * 192];   // high-path QKV     [p][s*64+h*16+d]

// -------------------- scalar helpers ---------------------------------------
__device__ __forceinline__ float dot4(float4 a, float4 b) {
    return a.x*b.x + a.y*b.y + a.z*b.z + a.w*b.w;
}
__device__ __forceinline__ void fma4(float4& a, float s, float4 v) {
    a.x = fmaf(s, v.x, a.x); a.y = fmaf(s, v.y, a.y);
    a.z = fmaf(s, v.z, a.z); a.w = fmaf(s, v.w, a.w);
}
__device__ __forceinline__ void scale4(float4& a, float s) {
    a.x *= s; a.y *= s; a.z *= s; a.w *= s;
}

// -------------------- packed f32x2 helpers (sm_100+ PTX) --------------------
__device__ __forceinline__ u64 pack2(float lo, float hi) {
    u64 r; asm("mov.b64 %0, {%1, %2};" : "=l"(r) : "f"(lo), "f"(hi)); return r;
}
__device__ __forceinline__ void unpack2(u64 v, float& lo, float& hi) {
    asm("mov.b64 {%0, %1}, %2;" : "=f"(lo), "=f"(hi) : "l"(v));
}
__device__ __forceinline__ u64 fma2(u64 a, u64 b, u64 c) {
    u64 d; asm("fma.rn.f32x2 %0, %1, %2, %3;" : "=l"(d) : "l"(a), "l"(b), "l"(c)); return d;
}
__device__ __forceinline__ u64 mul2(u64 a, u64 b) {
    u64 d; asm("mul.rn.f32x2 %0, %1, %2;" : "=l"(d) : "l"(a), "l"(b)); return d;
}

// -------------------- avg pool 2x2 -----------------------------------------
__global__ void pool_kernel(const float* __restrict__ x, float* __restrict__ low) {
    int m = blockIdx.x;          // pooled token 0..2303
    int c = threadIdx.x;         // channel 0..127
    int hs = m / 48, ws = m % 48;
    int p00 = (2*hs) * 96 + 2*ws;
    float v = x[p00*128 + c] + x[(p00+1)*128 + c]
            + x[(p00+96)*128 + c] + x[(p00+97)*128 + c];
    low[m*128 + c] = 0.25f * v;
}

// -------------------- pixel shuffle gather ----------------------------------
__global__ void l2h_kernel(const float* __restrict__ low, float* __restrict__ l2h) {
    int idx = blockIdx.x * blockDim.x + threadIdx.x;
    if (idx >= NPIX * 32) return;
    int p = idx >> 5, i = idx & 31;
    int h = p / 96, w = p % 96;
    l2h[idx] = low[((h >> 1) * 48 + (w >> 1)) * 128 + i*4 + (h & 1)*2 + (w & 1)];
}

// -------------------- packed tiled GEMM: C = A @ W^T (+bias)(-sub) ----------
// A: M x K row-major;  W: N x K row-major;  C written at [m*ldc + coff + n]
// Inner loop uses FFMA2 pairs over the m-direction (a-pairs come free from smem).
template<int BM, int BN, int BK>
__global__ __launch_bounds__((BM/4)*(BN/4))
void gemm_kernel(const float* __restrict__ A, const float* __restrict__ Wm,
                 const float* __restrict__ bias, const float* __restrict__ sub,
                 float* __restrict__ Cp, int M, int N, int K, int ldc, int coff) {
    constexpr int THREADS = (BM/4) * (BN/4);
    __shared__ float As[BK][BM + 4];   // BM+4 even -> u64-aligned rows
    __shared__ float Ws[BK][BN + 4];
    int tid  = threadIdx.x;
    int tcol = tid % (BN/4);
    int trow = tid / (BN/4);
    int m0 = blockIdx.x * BM;
    int n0 = blockIdx.y * BN;
    u64 acc[2][4];
    #pragma unroll
    for (int i = 0; i < 2; i++)
        #pragma unroll
        for (int j = 0; j < 4; j++) acc[i][j] = pack2(0.f, 0.f);

    for (int k0 = 0; k0 < K; k0 += BK) {
        for (int i = tid; i < BM * BK / 4; i += THREADS) {
            int m  = i / (BK/4);
            int kq = i % (BK/4);
            float4 v = *(const float4*)&A[(m0+m)*K + k0 + kq*4];
            As[kq*4+0][m] = v.x; As[kq*4+1][m] = v.y;
            As[kq*4+2][m] = v.z; As[kq*4+3][m] = v.w;
        }
        for (int i = tid; i < BN * BK / 4; i += THREADS) {
            int n  = i / (BK/4);
            int kq = i % (BK/4);
            float4 v = *(const float4*)&Wm[(n0+n)*K + k0 + kq*4];
            Ws[kq*4+0][n] = v.x; Ws[kq*4+1][n] = v.y;
            Ws[kq*4+2][n] = v.z; Ws[kq*4+3][n] = v.w;
        }
        __syncthreads();
        #pragma unroll
        for (int k = 0; k < BK; k++) {
            const u64* ap = (const u64*)&As[k][trow*4];   // rows (0,1),(2,3)
            u64 a01 = ap[0], a23 = ap[1];
            float4 wv = *(const float4*)&Ws[k][tcol*4];
            u64 w0 = pack2(wv.x, wv.x), w1 = pack2(wv.y, wv.y);
            u64 w2 = pack2(wv.z, wv.z), w3 = pack2(wv.w, wv.w);
            acc[0][0] = fma2(a01, w0, acc[0][0]);  acc[1][0] = fma2(a23, w0, acc[1][0]);
            acc[0][1] = fma2(a01, w1, acc[0][1]);  acc[1][1] = fma2(a23, w1, acc[1][1]);
            acc[0][2] = fma2(a01, w2, acc[0][2]);  acc[1][2] = fma2(a23, w2, acc[1][2]);
            acc[0][3] = fma2(a01, w3, acc[0][3]);  acc[1][3] = fma2(a23, w3, acc[1][3]);
        }
        __syncthreads();
    }

    float c[4][4];
    #pragma unroll
    for (int j = 0; j < 4; j++) {
        unpack2(acc[0][j], c[0][j], c[1][j]);
        unpack2(acc[1][j], c[2][j], c[3][j]);
    }
    int nb = n0 + tcol*4;
    float4 b4 = bias ? *(const float4*)&bias[nb] : make_float4(0,0,0,0);
    #pragma unroll
    for (int i = 0; i < 4; i++) {
        int m = m0 + trow*4 + i;
        float4 r = make_float4(c[i][0]+b4.x, c[i][1]+b4.y, c[i][2]+b4.z, c[i][3]+b4.w);
        if (sub) {
            float4 s4 = *(const float4*)&sub[m*ldc + coff + nb];
            r.x -= s4.x; r.y -= s4.y; r.z -= s4.z; r.w -= s4.w;
        }
        *(float4*)&Cp[m*ldc + coff + nb] = r;
    }
}

// -------------------- low attention + fused l_proj ---------------------------
// 144 blocks x 256 threads. Thread = (query qi 0..63, head 0..3).
// Phase A: flash attention over pooled KV (shared 64-token tile, all heads).
// Phase B: stage lxp in smem, apply l_proj 64x64 in-block, write out[:,0:64].
__global__ __launch_bounds__(256)
void low_attn_fused(const float* __restrict__ lq, const float* __restrict__ lkv,
                    const float* __restrict__ lproj, const float* __restrict__ lbias,
                    float* __restrict__ out) {
    __shared__ __align__(16) char sm[64*65*4 + 64*64*4];   // 33.3 KB, phase-aliased
    u64* Ks = (u64*)sm;              // [64 tok][32 u64] = 16 KB
    u64* Vs = (u64*)(sm + 16384);    // [64 tok][32 u64] = 16 KB
    int t = threadIdx.x;
    int qi = t & 63, head = t >> 6;
    int q = blockIdx.x * 64 + qi;

    u64 q2[8];
    {
        const u64* qp = (const u64*)&lq[q*64 + head*16];
        u64 s2 = pack2(ATTN_SCALE, ATTN_SCALE);
        #pragma unroll
        for (int i = 0; i < 8; i++) q2[i] = mul2(qp[i], s2);
    }
    u64 acc[8];
    #pragma unroll
    for (int i = 0; i < 8; i++) acc[i] = pack2(0.f, 0.f);
    float lsum = 0.f;

    for (int tk = 0; tk < NS; tk += 64) {
        __syncthreads();
        #pragma unroll
        for (int i = t; i < 64*32; i += 256) {     // 2048 float4
            int row = i >> 5, part = i & 31;
            float4 v = *(const float4*)&lkv[(tk + row)*128 + part*4];
            if (part < 16) *(float4*)&Ks[row*32 + part*2]      = v;
            else           *(float4*)&Vs[row*32 + (part-16)*2] = v;
        }
        __syncthreads();
        #pragma unroll 2
        for (int j = 0; j < 64; j++) {
            const u64* kr = &Ks[j*32 + head*8];    // broadcast within warp
            u64 d2 = mul2(q2[0], kr[0]);
            #pragma unroll
            for (int i = 1; i < 8; i++) d2 = fma2(q2[i], kr[i], d2);
            float lo, hi; unpack2(d2, lo, hi);
            float e = __expf(lo + hi);             // logits ~|0.1|: safe w/o max-sub
            lsum += e;
            u64 e2 = pack2(e, e);
            const u64* vr = &Vs[j*32 + head*8];
            #pragma unroll
            for (int i = 0; i < 8; i++) acc[i] = fma2(e2, vr[i], acc[i]);
        }
    }
    float myout[16];
    {
        u64 inv2 = pack2(1.f/lsum, 1.f/lsum);
        #pragma unroll
        for (int i = 0; i < 8; i++) {
            u64 r = mul2(acc[i], inv2);
            unpack2(r, myout[2*i], myout[2*i+1]);
        }
    }

    __syncthreads();                              // done reading Ks/Vs
    float* lxp_s = (float*)sm;                    // [64][65] (pad -> conflict-free)
    float* lp_s  = (float*)(sm + 64*65*4);        // [64 d][64 o] transposed proj
    #pragma unroll
    for (int i = 0; i < 16; i++) lxp_s[qi*65 + head*16 + i] = myout[i];
    for (int idx = t; idx < 4096; idx += 256) {
        int o = idx >> 6, d = idx & 63;
        lp_s[d*64 + o] = lproj[o*64 + d];
    }
    __syncthreads();

    // epilogue: out[q][o] = sum_d lxp[q][d] * proj[o][d] + b[o], o in [head*16, +16)
    u64 o2[8];
    {
        const u64* bp = (const u64*)&lbias[head*16];
        #pragma unroll
        for (int i = 0; i < 8; i++) o2[i] = bp[i];
    }
    for (int d = 0; d < 64; d++) {
        float a = lxp_s[qi*65 + d];
        u64 a2 = pack2(a, a);
        const u64* w2 = (const u64*)&lp_s[d*64 + head*16];
        #pragma unroll
        for (int i = 0; i < 8; i++) o2[i] = fma2(a2, w2[i], o2[i]);
    }
    u64* op = (u64*)&out[q*128 + head*16];
    #pragma unroll
    for (int i = 0; i < 8; i++) op[i] = o2[i];
}

// -------------------- high attention + fused h_proj --------------------------
// 144 blocks x 256 threads. Phase A thread = (wslot 0..15, head 0..3, r 0..3):
// 2x2 windowed attention for pixel p(wslot,r). Phase B: h_proj per pixel.
__global__ __launch_bounds__(256)
void high_attn_fused(const float* __restrict__ hqkv, const float* __restrict__ hproj,
                     const float* __restrict__ hbias, float* __restrict__ out) {
    __shared__ float ho_s[64*65];
    __shared__ float hp_s[64*64];
    int t = threadIdx.x;
    int r = t & 3, head = (t >> 2) & 3, wslot = t >> 4;
    int g = blockIdx.x * 16 + wslot;
    int hg = g / 48, wg = g % 48;
    int p = (hg*2 + (r >> 1)) * 96 + wg*2 + (r & 1);

    const float4* qp = (const float4*)&hqkv[p*192 + head*16];
    float4 q0 = qp[0], q1 = qp[1], q2 = qp[2], q3 = qp[3];
    scale4(q0, ATTN_SCALE); scale4(q1, ATTN_SCALE);
    scale4(q2, ATTN_SCALE); scale4(q3, ATTN_SCALE);

    float e[4]; int pid[4]; float lsum = 0.f;
    #pragma unroll
    for (int rr = 0; rr < 4; rr++) {
        int pp = (hg*2 + (rr >> 1)) * 96 + wg*2 + (rr & 1);
        pid[rr] = pp;
        const float4* kp = (const float4*)&hqkv[pp*192 + 64 + head*16];
        float s = (dot4(q0, kp[0]) + dot4(q1, kp[1]))
                + (dot4(q2, kp[2]) + dot4(q3, kp[3]));
        e[rr] = __expf(s);
        lsum += e[rr];
    }
    float4 a0 = {0,0,0,0}, a1 = {0,0,0,0}, a2 = {0,0,0,0}, a3 = {0,0,0,0};
    #pragma unroll
    for (int rr = 0; rr < 4; rr++) {
        const float4* vp = (const float4*)&hqkv[pid[rr]*192 + 128 + head*16];
        fma4(a0, e[rr], vp[0]); fma4(a1, e[rr], vp[1]);
        fma4(a2, e[rr], vp[2]); fma4(a3, e[rr], vp[3]);
    }
    float inv = 1.f / lsum;
    scale4(a0, inv); scale4(a1, inv); scale4(a2, inv); scale4(a3, inv);

    int px = wslot*4 + r;
    float* hrow = &ho_s[px*65 + head*16];
    hrow[0]  = a0.x; hrow[1]  = a0.y; hrow[2]  = a0.z; hrow[3]  = a0.w;
    hrow[4]  = a1.x; hrow[5]  = a1.y; hrow[6]  = a1.z; hrow[7]  = a1.w;
    hrow[8]  = a2.x; hrow[9]  = a2.y; hrow[10] = a2.z; hrow[11] = a2.w;
    hrow[12] = a3.x; hrow[13] = a3.y; hrow[14] = a3.z; hrow[15] = a3.w;

    for (int idx = t; idx < 4096; idx += 256) {
        int o = idx >> 6, d = idx & 63;
        hp_s[d*64 + o] = hproj[o*64 + d];
    }
    __syncthreads();

    // epilogue: thread -> (px2 = t&63, og = t>>6)
    int px2 = t & 63, og = t >> 6;
    int wslot2 = px2 >> 2, r2 = px2 & 3;
    int g2 = blockIdx.x * 16 + wslot2;
    int hg2 = g2 / 48, wg2 = g2 % 48;
    int p2 = (hg2*2 + (r2 >> 1)) * 96 + wg2*2 + (r2 & 1);

    u64 o2[8];
    {
        const u64* bp = (const u64*)&hbias[og*16];
        #pragma unroll
        for (int i = 0; i < 8; i++) o2[i] = bp[i];
    }
    for (int d = 0; d < 64; d++) {
        float a = ho_s[px2*65 + d];
        u64 a2v = pack2(a, a);
        const u64* w2 = (const u64*)&hp_s[d*64 + og*16];
        #pragma unroll
        for (int i = 0; i < 8; i++) o2[i] = fma2(a2v, w2[i], o2[i]);
    }
    u64* op = (u64*)&out[p2*128 + 64 + og*16];
    #pragma unroll
    for (int i = 0; i < 8; i++) op[i] = o2[i];
}

// -------------------- launch -------------------------------------------------
extern "C" void kernel_launch(void* const* d_in, const int* in_sizes, int n_in,
                              void* d_out, int out_size) {
    const float* x         = (const float*)d_in[0];
    const float* restore_w = (const float*)d_in[1];
    const float* restore_b = (const float*)d_in[2];
    const float* l_q_w     = (const float*)d_in[3];
    const float* l_kv_w    = (const float*)d_in[4];
    const float* l_proj_w  = (const float*)d_in[5];
    const float* l_proj_b  = (const float*)d_in[6];
    const float* h_qkv_w   = (const float*)d_in[7];
    const float* h_proj_w  = (const float*)d_in[8];
    const float* h_proj_b  = (const float*)d_in[9];
    float* out = (float*)d_out;

    float *low, *l2h, *high, *lq, *lkv, *hqkv;
    cudaGetSymbolAddress((void**)&low,  g_low);
    cudaGetSymbolAddress((void**)&l2h,  g_l2h);
    cudaGetSymbolAddress((void**)&high, g_high);
    cudaGetSymbolAddress((void**)&lq,   g_lq);
    cudaGetSymbolAddress((void**)&lkv,  g_lkv);
    cudaGetSymbolAddress((void**)&hqkv, g_hqkv);

    // 1. pooled low features
    pool_kernel<<<NS, 128>>>(x, low);
    // 2. pixel-shuffle gather
    l2h_kernel<<<(NPIX*32 + 255)/256, 256>>>(low, l2h);
    // 3. low-path queries: x @ l_q_w^T           (9216 x 64 x 128)
    gemm_kernel<64,64,32><<<dim3(144,1), 256>>>(x, l_q_w, nullptr, nullptr,
                                                lq, NPIX, 64, 128, 64, 0);
    // 4. low-path KV: low @ l_kv_w^T             (2304 x 128 x 128)
    gemm_kernel<32,64,32><<<dim3(72,2), 128>>>(low, l_kv_w, nullptr, nullptr,
                                               lkv, NS, 128, 128, 128, 0);
    // 5. high residual: l2h @ restore_w^T + b - x (9216 x 128 x 32)
    gemm_kernel<64,64,32><<<dim3(144,2), 256>>>(l2h, restore_w, restore_b, x,
                                                high, NPIX, 128, 32, 128, 0);
    // 6. high QKV: high @ h_qkv_w^T              (9216 x 192 x 128)
    gemm_kernel<64,64,32><<<dim3(144,3), 256>>>(high, h_qkv_w, nullptr, nullptr,
                                                hqkv, NPIX, 192, 128, 192, 0);
    // 7. low attention + l_proj -> out[:, 0:64]
    low_attn_fused<<<144, 256>>>(lq, lkv, l_proj_w, l_proj_b, out);
    // 8. high attention + h_proj -> out[:, 64:128]
    high_attn_fused<<<144, 256>>>(hqkv, h_proj_w, h_proj_b, out);
}

// round 13
// speedup vs baseline: 1.5666x; 1.5666x over previous
#include <cuda_runtime.h>
#include <cstdint>

// ---------------------------------------------------------------------------
// HiLo attention block, B=1, H=W=96, DIM=128, WS=2
// ---------------------------------------------------------------------------

#define NPIX 9216          // 96*96
#define NS   2304          // 48*48 pooled tokens
#define ATTN_SCALE 0.25f   // 16^-0.5

typedef unsigned long long u64;

// -------------------- scratch (device globals; no allocation) --------------
__device__ float g_low [NS   * 128];   // pooled features
__device__ float g_l2h [NPIX * 32];    // pixel-shuffled low
__device__ float g_high[NPIX * 128];   // high-frequency residual
__device__ float g_lq  [NPIX * 64];    // low-path queries  [n][h*16+d]
__device__ float g_lkv [NS   * 128];   // low-path K|V      [m][kv*64+h*16+d]
__device__ float g_hqkv[NPIX * 192];   // high-path QKV     [p][s*64+h*16+d]

// -------------------- scalar helpers ---------------------------------------
__device__ __forceinline__ float dot4(float4 a, float4 b) {
    return a.x*b.x + a.y*b.y + a.z*b.z + a.w*b.w;
}
__device__ __forceinline__ void fma4(float4& a, float s, float4 v) {
    a.x = fmaf(s, v.x, a.x); a.y = fmaf(s, v.y, a.y);
    a.z = fmaf(s, v.z, a.z); a.w = fmaf(s, v.w, a.w);
}
__device__ __forceinline__ void scale4(float4& a, float s) {
    a.x *= s; a.y *= s; a.z *= s; a.w *= s;
}

// -------------------- packed f32x2 helpers (sm_100+ PTX) --------------------
__device__ __forceinline__ u64 pack2(float lo, float hi) {
    u64 r; asm("mov.b64 %0, {%1, %2};" : "=l"(r) : "f"(lo), "f"(hi)); return r;
}
__device__ __forceinline__ void unpack2(u64 v, float& lo, float& hi) {
    asm("mov.b64 {%0, %1}, %2;" : "=f"(lo), "=f"(hi) : "l"(v));
}
__device__ __forceinline__ u64 fma2(u64 a, u64 b, u64 c) {
    u64 d; asm("fma.rn.f32x2 %0, %1, %2, %3;" : "=l"(d) : "l"(a), "l"(b), "l"(c)); return d;
}
__device__ __forceinline__ u64 mul2(u64 a, u64 b) {
    u64 d; asm("mul.rn.f32x2 %0, %1, %2;" : "=l"(d) : "l"(a), "l"(b)); return d;
}

// -------------------- cp.async helpers --------------------------------------
#define CP_ASYNC16(saddr, gptr) \
    asm volatile("cp.async.cg.shared.global [%0], [%1], 16;" :: "r"(saddr), "l"(gptr))
#define CP_COMMIT() asm volatile("cp.async.commit_group;")
#define CP_WAIT(n)  asm volatile("cp.async.wait_group %0;" :: "n"(n))

// -------------------- avg pool 2x2 -----------------------------------------
__global__ void pool_kernel(const float* __restrict__ x, float* __restrict__ low) {
    int m = blockIdx.x;          // pooled token 0..2303
    int c = threadIdx.x;         // channel 0..127
    int hs = m / 48, ws = m % 48;
    int p00 = (2*hs) * 96 + 2*ws;
    float v = x[p00*128 + c] + x[(p00+1)*128 + c]
            + x[(p00+96)*128 + c] + x[(p00+97)*128 + c];
    low[m*128 + c] = 0.25f * v;
}

// -------------------- pixel shuffle gather ----------------------------------
__global__ void l2h_kernel(const float* __restrict__ low, float* __restrict__ l2h) {
    int idx = blockIdx.x * blockDim.x + threadIdx.x;
    if (idx >= NPIX * 32) return;
    int p = idx >> 5, i = idx & 31;
    int h = p / 96, w = p % 96;
    l2h[idx] = low[((h >> 1) * 48 + (w >> 1)) * 128 + i*4 + (h & 1)*2 + (w & 1)];
}

// -------------------- packed tiled GEMM with register double-buffering ------
// C = A @ W^T (+bias)(-sub).  A: MxK row-major, W: NxK row-major.
template<int BM, int BN, int BK>
__global__ __launch_bounds__((BM/4)*(BN/4))
void gemm_kernel(const float* __restrict__ A, const float* __restrict__ Wm,
                 const float* __restrict__ bias, const float* __restrict__ sub,
                 float* __restrict__ Cp, int M, int N, int K, int ldc, int coff) {
    constexpr int THREADS = (BM/4) * (BN/4);
    constexpr int AC = (BM * BK / 4) / THREADS;
    constexpr int WC = (BN * BK / 4) / THREADS;
    __shared__ float As[BK][BM + 4];   // transposed, u64-aligned rows
    __shared__ float Ws[BK][BN + 4];
    int tid  = threadIdx.x;
    int tcol = tid % (BN/4);
    int trow = tid / (BN/4);
    int m0 = blockIdx.x * BM;
    int n0 = blockIdx.y * BN;

    float4 pa[AC], pw[WC];
    #pragma unroll
    for (int c = 0; c < AC; c++) {
        int i = tid + c*THREADS, m = i/(BK/4), kq = i%(BK/4);
        pa[c] = *(const float4*)&A[(m0+m)*K + kq*4];
    }
    #pragma unroll
    for (int c = 0; c < WC; c++) {
        int i = tid + c*THREADS, n = i/(BK/4), kq = i%(BK/4);
        pw[c] = *(const float4*)&Wm[(n0+n)*K + kq*4];
    }

    u64 acc[2][4];
    #pragma unroll
    for (int i = 0; i < 2; i++)
        #pragma unroll
        for (int j = 0; j < 4; j++) acc[i][j] = pack2(0.f, 0.f);

    for (int k0 = 0; k0 < K; k0 += BK) {
        // store prefetched tile to smem (transposed)
        #pragma unroll
        for (int c = 0; c < AC; c++) {
            int i = tid + c*THREADS, m = i/(BK/4), kq = i%(BK/4);
            As[kq*4+0][m] = pa[c].x; As[kq*4+1][m] = pa[c].y;
            As[kq*4+2][m] = pa[c].z; As[kq*4+3][m] = pa[c].w;
        }
        #pragma unroll
        for (int c = 0; c < WC; c++) {
            int i = tid + c*THREADS, n = i/(BK/4), kq = i%(BK/4);
            Ws[kq*4+0][n] = pw[c].x; Ws[kq*4+1][n] = pw[c].y;
            Ws[kq*4+2][n] = pw[c].z; Ws[kq*4+3][n] = pw[c].w;
        }
        // issue next-tile loads (latency overlaps compute below)
        if (k0 + BK < K) {
            #pragma unroll
            for (int c = 0; c < AC; c++) {
                int i = tid + c*THREADS, m = i/(BK/4), kq = i%(BK/4);
                pa[c] = *(const float4*)&A[(m0+m)*K + k0 + BK + kq*4];
            }
            #pragma unroll
            for (int c = 0; c < WC; c++) {
                int i = tid + c*THREADS, n = i/(BK/4), kq = i%(BK/4);
                pw[c] = *(const float4*)&Wm[(n0+n)*K + k0 + BK + kq*4];
            }
        }
        __syncthreads();
        #pragma unroll
        for (int k = 0; k < BK; k++) {
            const u64* ap = (const u64*)&As[k][trow*4];
            u64 a01 = ap[0], a23 = ap[1];
            float4 wv = *(const float4*)&Ws[k][tcol*4];
            u64 w0 = pack2(wv.x, wv.x), w1 = pack2(wv.y, wv.y);
            u64 w2 = pack2(wv.z, wv.z), w3 = pack2(wv.w, wv.w);
            acc[0][0] = fma2(a01, w0, acc[0][0]);  acc[1][0] = fma2(a23, w0, acc[1][0]);
            acc[0][1] = fma2(a01, w1, acc[0][1]);  acc[1][1] = fma2(a23, w1, acc[1][1]);
            acc[0][2] = fma2(a01, w2, acc[0][2]);  acc[1][2] = fma2(a23, w2, acc[1][2]);
            acc[0][3] = fma2(a01, w3, acc[0][3]);  acc[1][3] = fma2(a23, w3, acc[1][3]);
        }
        __syncthreads();
    }

    float c[4][4];
    #pragma unroll
    for (int j = 0; j < 4; j++) {
        unpack2(acc[0][j], c[0][j], c[1][j]);
        unpack2(acc[1][j], c[2][j], c[3][j]);
    }
    int nb = n0 + tcol*4;
    float4 b4 = bias ? *(const float4*)&bias[nb] : make_float4(0,0,0,0);
    #pragma unroll
    for (int i = 0; i < 4; i++) {
        int m = m0 + trow*4 + i;
        float4 r = make_float4(c[i][0]+b4.x, c[i][1]+b4.y, c[i][2]+b4.z, c[i][3]+b4.w);
        if (sub) {
            float4 s4 = *(const float4*)&sub[m*ldc + coff + nb];
            r.x -= s4.x; r.y -= s4.y; r.z -= s4.z; r.w -= s4.w;
        }
        *(float4*)&Cp[m*ldc + coff + nb] = r;
    }
}

// -------------------- low attention + fused l_proj ---------------------------
// 144 blocks x 128 threads. Thread = (query-pair qp 0..31, head = warp 0..3).
// KV tiles of 48 keys, cp.async double-buffered. 2 queries/thread amortize
// all K/V smem reads. Epilogue applies l_proj in-block -> out[:, 0:64].
__global__ __launch_bounds__(128)
void low_attn_fused(const float* __restrict__ lq, const float* __restrict__ lkv,
                    const float* __restrict__ lproj, const float* __restrict__ lbias,
                    float* __restrict__ out) {
    __shared__ __align__(16) char sm[49152];         // 2 x 24 KB KV buffers
    uint32_t sbase = (uint32_t)__cvta_generic_to_shared(sm);
    int t = threadIdx.x;
    int qp = t & 31, head = t >> 5;                  // head uniform per warp
    int qa = blockIdx.x * 64 + qp * 2;               // queries qa, qa+1

    u64 qA[8], qB[8];
    {
        const u64* p0 = (const u64*)&lq[qa*64 + head*16];
        const u64* p1 = (const u64*)&lq[(qa+1)*64 + head*16];
        u64 s2 = pack2(ATTN_SCALE, ATTN_SCALE);
        #pragma unroll
        for (int i = 0; i < 8; i++) { qA[i] = mul2(p0[i], s2); qB[i] = mul2(p1[i], s2); }
    }
    u64 accA[8], accB[8];
    #pragma unroll
    for (int i = 0; i < 8; i++) { accA[i] = pack2(0.f,0.f); accB[i] = pack2(0.f,0.f); }
    float lsA = 0.f, lsB = 0.f;

    // prefetch tile 0 (48 rows x 128 floats = 1536 float4, 12 per thread)
    #pragma unroll
    for (int c = 0; c < 12; c++) {
        int i = t + c*128, row = i >> 5, part = i & 31;
        CP_ASYNC16(sbase + (row*128 + part*4)*4, (const float4*)&lkv[row*128 + part*4]);
    }
    CP_COMMIT();

    for (int tile = 0; tile < 48; tile++) {
        if (tile < 47) {
            int tk = (tile + 1) * 48;
            uint32_t dst = sbase + (uint32_t)(((tile+1) & 1) * 24576);
            #pragma unroll
            for (int c = 0; c < 12; c++) {
                int i = t + c*128, row = i >> 5, part = i & 31;
                CP_ASYNC16(dst + (row*128 + part*4)*4,
                           (const float4*)&lkv[(tk+row)*128 + part*4]);
            }
            CP_COMMIT();
            CP_WAIT(1);            // current tile's group done, next in flight
        } else {
            CP_WAIT(0);
        }
        __syncthreads();
        const float* B = (const float*)(sm + (tile & 1) * 24576);
        #pragma unroll 2
        for (int j = 0; j < 48; j++) {
            const u64* kr = (const u64*)&B[j*128 + head*16];      // warp broadcast
            u64 dA = mul2(qA[0], kr[0]), dB = mul2(qB[0], kr[0]);
            #pragma unroll
            for (int i = 1; i < 8; i++) {
                dA = fma2(qA[i], kr[i], dA);
                dB = fma2(qB[i], kr[i], dB);
            }
            float a0,a1,b0,b1; unpack2(dA,a0,a1); unpack2(dB,b0,b1);
            float eA = __expf(a0+a1), eB = __expf(b0+b1);   // logits ~|0.1|
            lsA += eA; lsB += eB;
            u64 eA2 = pack2(eA,eA), eB2 = pack2(eB,eB);
            const u64* vr = (const u64*)&B[j*128 + 64 + head*16];
            #pragma unroll
            for (int i = 0; i < 8; i++) {
                accA[i] = fma2(eA2, vr[i], accA[i]);
                accB[i] = fma2(eB2, vr[i], accB[i]);
            }
        }
        __syncthreads();
    }

    float oA[16], oB[16];
    {
        u64 iA = pack2(1.f/lsA, 1.f/lsA), iB = pack2(1.f/lsB, 1.f/lsB);
        #pragma unroll
        for (int i = 0; i < 8; i++) {
            u64 rA = mul2(accA[i], iA), rB = mul2(accB[i], iB);
            unpack2(rA, oA[2*i], oA[2*i+1]);
            unpack2(rB, oB[2*i], oB[2*i+1]);
        }
    }

    // ---- fused projection (smem re-used; loop ended with __syncthreads) ----
    float* lxp_s = (float*)sm;                    // [64][65]
    float* lp_s  = (float*)(sm + 64*65*4);        // [64 d][64 o] transposed
    #pragma unroll
    for (int i = 0; i < 16; i++) {
        lxp_s[(qp*2  )*65 + head*16 + i] = oA[i];
        lxp_s[(qp*2+1)*65 + head*16 + i] = oB[i];
    }
    for (int idx = t; idx < 4096; idx += 128) {
        int o = idx >> 6, d = idx & 63;
        lp_s[d*64 + o] = lproj[o*64 + d];
    }
    __syncthreads();

    u64 o2A[8], o2B[8];
    {
        const u64* bp = (const u64*)&lbias[head*16];
        #pragma unroll
        for (int i = 0; i < 8; i++) { o2A[i] = bp[i]; o2B[i] = bp[i]; }
    }
    for (int d = 0; d < 64; d++) {
        float aA = lxp_s[(qp*2)*65 + d], aB = lxp_s[(qp*2+1)*65 + d];
        u64 aA2 = pack2(aA,aA), aB2 = pack2(aB,aB);
        const u64* w2 = (const u64*)&lp_s[d*64 + head*16];        // warp broadcast
        #pragma unroll
        for (int i = 0; i < 8; i++) {
            o2A[i] = fma2(aA2, w2[i], o2A[i]);
            o2B[i] = fma2(aB2, w2[i], o2B[i]);
        }
    }
    u64* opA = (u64*)&out[qa*128 + head*16];
    u64* opB = (u64*)&out[(qa+1)*128 + head*16];
    #pragma unroll
    for (int i = 0; i < 8; i++) { opA[i] = o2A[i]; opB[i] = o2B[i]; }
}

// -------------------- high attention + fused h_proj --------------------------
// 144 blocks x 256 threads. Phase A thread = (wslot 0..15, head 0..3, r 0..3).
__global__ __launch_bounds__(256)
void high_attn_fused(const float* __restrict__ hqkv, const float* __restrict__ hproj,
                     const float* __restrict__ hbias, float* __restrict__ out) {
    __shared__ float ho_s[64*65];
    __shared__ float hp_s[64*64];
    int t = threadIdx.x;
    int r = t & 3, head = (t >> 2) & 3, wslot = t >> 4;
    int g = blockIdx.x * 16 + wslot;
    int hg = g / 48, wg = g % 48;
    int p = (hg*2 + (r >> 1)) * 96 + wg*2 + (r & 1);

    const float4* qp = (const float4*)&hqkv[p*192 + head*16];
    float4 q0 = qp[0], q1 = qp[1], q2 = qp[2], q3 = qp[3];
    scale4(q0, ATTN_SCALE); scale4(q1, ATTN_SCALE);
    scale4(q2, ATTN_SCALE); scale4(q3, ATTN_SCALE);

    float e[4]; int pid[4]; float lsum = 0.f;
    #pragma unroll
    for (int rr = 0; rr < 4; rr++) {
        int pp = (hg*2 + (rr >> 1)) * 96 + wg*2 + (rr & 1);
        pid[rr] = pp;
        const float4* kp = (const float4*)&hqkv[pp*192 + 64 + head*16];
        float s = (dot4(q0, kp[0]) + dot4(q1, kp[1]))
                + (dot4(q2, kp[2]) + dot4(q3, kp[3]));
        e[rr] = __expf(s);
        lsum += e[rr];
    }
    float4 a0 = {0,0,0,0}, a1 = {0,0,0,0}, a2 = {0,0,0,0}, a3 = {0,0,0,0};
    #pragma unroll
    for (int rr = 0; rr < 4; rr++) {
        const float4* vp = (const float4*)&hqkv[pid[rr]*192 + 128 + head*16];
        fma4(a0, e[rr], vp[0]); fma4(a1, e[rr], vp[1]);
        fma4(a2, e[rr], vp[2]); fma4(a3, e[rr], vp[3]);
    }
    float inv = 1.f / lsum;
    scale4(a0, inv); scale4(a1, inv); scale4(a2, inv); scale4(a3, inv);

    int px = wslot*4 + r;
    float* hrow = &ho_s[px*65 + head*16];
    hrow[0]  = a0.x; hrow[1]  = a0.y; hrow[2]  = a0.z; hrow[3]  = a0.w;
    hrow[4]  = a1.x; hrow[5]  = a1.y; hrow[6]  = a1.z; hrow[7]  = a1.w;
    hrow[8]  = a2.x; hrow[9]  = a2.y; hrow[10] = a2.z; hrow[11] = a2.w;
    hrow[12] = a3.x; hrow[13] = a3.y; hrow[14] = a3.z; hrow[15] = a3.w;

    for (int idx = t; idx < 4096; idx += 256) {
        int o = idx >> 6, d = idx & 63;
        hp_s[d*64 + o] = hproj[o*64 + d];
    }
    __syncthreads();

    int px2 = t & 63, og = t >> 6;
    int wslot2 = px2 >> 2, r2 = px2 & 3;
    int g2 = blockIdx.x * 16 + wslot2;
    int hg2 = g2 / 48, wg2 = g2 % 48;
    int p2 = (hg2*2 + (r2 >> 1)) * 96 + wg2*2 + (r2 & 1);

    u64 o2[8];
    {
        const u64* bp = (const u64*)&hbias[og*16];
        #pragma unroll
        for (int i = 0; i < 8; i++) o2[i] = bp[i];
    }
    for (int d = 0; d < 64; d++) {
        float a = ho_s[px2*65 + d];
        u64 a2v = pack2(a, a);
        const u64* w2 = (const u64*)&hp_s[d*64 + og*16];
        #pragma unroll
        for (int i = 0; i < 8; i++) o2[i] = fma2(a2v, w2[i], o2[i]);
    }
    u64* op = (u64*)&out[p2*128 + 64 + og*16];
    #pragma unroll
    for (int i = 0; i < 8; i++) op[i] = o2[i];
}

// -------------------- launch -------------------------------------------------
extern "C" void kernel_launch(void* const* d_in, const int* in_sizes, int n_in,
                              void* d_out, int out_size) {
    const float* x         = (const float*)d_in[0];
    const float* restore_w = (const float*)d_in[1];
    const float* restore_b = (const float*)d_in[2];
    const float* l_q_w     = (const float*)d_in[3];
    const float* l_kv_w    = (const float*)d_in[4];
    const float* l_proj_w  = (const float*)d_in[5];
    const float* l_proj_b  = (const float*)d_in[6];
    const float* h_qkv_w   = (const float*)d_in[7];
    const float* h_proj_w  = (const float*)d_in[8];
    const float* h_proj_b  = (const float*)d_in[9];
    float* out = (float*)d_out;

    float *low, *l2h, *high, *lq, *lkv, *hqkv;
    cudaGetSymbolAddress((void**)&low,  g_low);
    cudaGetSymbolAddress((void**)&l2h,  g_l2h);
    cudaGetSymbolAddress((void**)&high, g_high);
    cudaGetSymbolAddress((void**)&lq,   g_lq);
    cudaGetSymbolAddress((void**)&lkv,  g_lkv);
    cudaGetSymbolAddress((void**)&hqkv, g_hqkv);

    // 1. pooled low features
    pool_kernel<<<NS, 128>>>(x, low);
    // 2. pixel-shuffle gather
    l2h_kernel<<<(NPIX*32 + 255)/256, 256>>>(low, l2h);
    // 3. low-path queries: x @ l_q_w^T           (9216 x 64 x 128)
    gemm_kernel<64,64,32><<<dim3(144,1), 256>>>(x, l_q_w, nullptr, nullptr,
                                                lq, NPIX, 64, 128, 64, 0);
    // 4. low-path KV: low @ l_kv_w^T             (2304 x 128 x 128)
    gemm_kernel<32,64,32><<<dim3(72,2), 128>>>(low, l_kv_w, nullptr, nullptr,
                                               lkv, NS, 128, 128, 128, 0);
    // 5. high residual: l2h @ restore_w^T + b - x (9216 x 128 x 32)
    gemm_kernel<64,64,32><<<dim3(144,2), 256>>>(l2h, restore_w, restore_b, x,
                                                high, NPIX, 128, 32, 128, 0);
    // 6. high QKV: high @ h_qkv_w^T              (9216 x 192 x 128)
    gemm_kernel<64,64,32><<<dim3(144,3), 256>>>(high, h_qkv_w, nullptr, nullptr,
                                                hqkv, NPIX, 192, 128, 192, 0);
    // 7. low attention + l_proj -> out[:, 0:64]
    low_attn_fused<<<144, 128>>>(lq, lkv, l_proj_w, l_proj_b, out);
    // 8. high attention + h_proj -> out[:, 64:128]
    high_attn_fused<<<144, 256>>>(hqkv, h_proj_w, h_proj_b, out);
}